// round 9
// baseline (speedup 1.0000x reference)
#include <cuda_runtime.h>
#include <cuda_bf16.h>
#include <cstdint>

// Problem shape (fixed)
#define BDIM 4096
#define DDIM 2048
#define LDIM 16384
#define KSEL 64

#define CAP   1024          // max candidates per row (expected ~400)
#define THR0  2.25f         // GEMM-epilogue candidate threshold on |z~|
#define MARGIN2 0.022f      // 2 * max|z~ - z| (bf16 GEMM error, 6.5 sigma)
#define ECAP  192           // max exact-recompute candidates per row (expected ~70)

// ---------------- device globals (scratch; no allocations allowed) ----------
__device__ __nv_bfloat16 g_Ah[(size_t)BDIM * DDIM];           // x in bf16
__device__ __nv_bfloat16 g_Bh[(size_t)LDIM * DDIM];           // W_enc^T bf16 (K-major)
__device__ float g_Wt[(size_t)LDIM * DDIM];                   // W_enc^T fp32 (exact dots)
__device__ int   g_cnt[BDIM];                                 // per-row candidate count
__device__ int   g_cidx[(size_t)BDIM * CAP];                  // candidate columns
__device__ float g_cval[(size_t)BDIM * CAP];                  // candidate approx values
__device__ int   g_topk_idx[BDIM * KSEL];
__device__ float g_topk_val[BDIM * KSEL];

// ---------------- helpers ----------------------------------------------------
__device__ __forceinline__ uint32_t smem_u32(const void* p) {
    uint32_t a;
    asm("{ .reg .u64 t; cvta.to.shared.u64 t, %1; cvt.u32.u64 %0, t; }" : "=r"(a) : "l"(p));
    return a;
}
#define SWZ128(o) ((o) ^ (((o) >> 3) & 0x70))

#define CP_ASYNC16(dst, src) \
    asm volatile("cp.async.cg.shared.global [%0], [%1], 16;" :: "r"(dst), "l"(src))
#define CP_COMMIT() asm volatile("cp.async.commit_group;" ::: "memory")
#define CP_WAIT2()  asm volatile("cp.async.wait_group 2;" ::: "memory")

#define LDSM_X4(r0, r1, r2, r3, addr) \
    asm volatile("ldmatrix.sync.aligned.m8n8.x4.shared.b16 {%0,%1,%2,%3}, [%4];" \
                 : "=r"(r0), "=r"(r1), "=r"(r2), "=r"(r3) : "r"(addr))

#define MMA16816(c, a, b0, b1) \
    asm volatile("mma.sync.aligned.m16n8k16.row.col.f32.bf16.bf16.f32 " \
                 "{%0,%1,%2,%3}, {%4,%5,%6,%7}, {%8,%9}, {%0,%1,%2,%3};" \
                 : "+f"((c)[0]), "+f"((c)[1]), "+f"((c)[2]), "+f"((c)[3]) \
                 : "r"((a)[0]), "r"((a)[1]), "r"((a)[2]), "r"((a)[3]), \
                   "r"(b0), "r"(b1))

// ---------------- small kernels ----------------------------------------------
__global__ __launch_bounds__(256) void init_cnt_kernel() {
    int i = blockIdx.x * 256 + threadIdx.x;
    if (i < BDIM) g_cnt[i] = 0;
}

__global__ __launch_bounds__(256) void zero_fill_kernel(float4* __restrict__ p) {
    size_t i = (size_t)blockIdx.x * 256 + threadIdx.x;
    p[i] = make_float4(0.f, 0.f, 0.f, 0.f);
}

__global__ __launch_bounds__(256) void convert_x_kernel(const float* __restrict__ x) {
    size_t i = (size_t)blockIdx.x * 256 + threadIdx.x;
    g_Ah[i] = __float2bfloat16(x[i]);
}

__global__ __launch_bounds__(256) void convert_w_kernel(const float* __restrict__ W) {
    __shared__ float t[32][33];
    const int l0 = blockIdx.x * 32;
    const int d0 = blockIdx.y * 32;
    const int tx = threadIdx.x, ty = threadIdx.y;   // (32, 8)
    #pragma unroll
    for (int i = 0; i < 4; i++)
        t[ty + i * 8][tx] = W[(size_t)(d0 + ty + i * 8) * LDIM + l0 + tx];
    __syncthreads();
    #pragma unroll
    for (int i = 0; i < 4; i++) {
        float v = t[tx][ty + i * 8];
        size_t o = (size_t)(l0 + ty + i * 8) * DDIM + d0 + tx;
        g_Bh[o] = __float2bfloat16(v);
        g_Wt[o] = v;
    }
}

// ---------------- bf16 mma.sync GEMM + fused candidate extraction ------------
// CTA 128x128, 8 warps (4 m x 2 n), warp tile 32x64, K-chunk 64, 4-stage cp.async
// Fragment loads double-buffered across ks steps.
#define S_STAGES 4
#define NCHUNK   32               // 2048 / 64
#define A_TILE_B 16384            // 128 rows * 128 B
#define STAGE_B  32768
#define GEMM_DSMEM (S_STAGES * STAGE_B + 1024)

extern __shared__ char gdsm[];

__global__ void __launch_bounds__(256, 1) encode_gemm_mma(const float* __restrict__ benc) {
    const int tid  = threadIdx.x;
    const int lane = tid & 31;
    const int wid  = tid >> 5;
    const int wm   = wid & 3;          // m offset 32*wm
    const int wn   = wid >> 2;         // n offset 64*wn
    const int mBase = blockIdx.y * 128;
    const int nBase = blockIdx.x * 128;

    const uint32_t base = (smem_u32(gdsm) + 1023u) & ~1023u;

    // precomputed intra-tile ldmatrix offsets (swizzled; row-dependent parts)
    const int a_row0 = wm * 32 + (lane & 15);            // + mt*16
    const int a_koff = (lane >> 4) << 4;                 // + ks*32
    const int b_n0   = wn * 64 + (lane & 7) + ((lane >> 4) << 3);  // + g*16
    const int b_koff = (lane & 8) << 1;                  // + ks*32

    auto load_chunk = [&](int c) {
        const int s  = c & (S_STAGES - 1);
        const int kk = c * 64;
        const uint32_t Ab = base + s * STAGE_B;
        const uint32_t Bb = Ab + A_TILE_B;
        #pragma unroll
        for (int i = 0; i < 8; i++) {
            int t = tid + i * 256;
            if (t < 1024) {                       // A: 128 rows x 8 x 16B
                int r = t >> 3, j = t & 7;
                CP_ASYNC16(Ab + SWZ128(r * 128 + j * 16),
                           g_Ah + ((size_t)(mBase + r) * DDIM + kk + j * 8));
            } else {                              // B: 128 rows x 8 x 16B
                int u = t - 1024;
                int r = u >> 3, j = u & 7;
                CP_ASYNC16(Bb + SWZ128(r * 128 + j * 16),
                           g_Bh + ((size_t)(nBase + r) * DDIM + kk + j * 8));
            }
        }
    };

    float acc[2][8][4];
    #pragma unroll
    for (int mt = 0; mt < 2; mt++)
        #pragma unroll
        for (int nt = 0; nt < 8; nt++)
            #pragma unroll
            for (int q = 0; q < 4; q++) acc[mt][nt][q] = 0.0f;

    uint32_t a[2][2][4], b[2][4][4];     // [buf][...]

    auto load_frags = [&](int buf, uint32_t Ab, uint32_t Bb, int ks) {
        #pragma unroll
        for (int mt = 0; mt < 2; mt++) {
            int row = a_row0 + mt * 16;
            LDSM_X4(a[buf][mt][0], a[buf][mt][1], a[buf][mt][2], a[buf][mt][3],
                    Ab + SWZ128(row * 128 + ks * 32 + a_koff));
        }
        #pragma unroll
        for (int g = 0; g < 4; g++) {
            int n = b_n0 + g * 16;
            LDSM_X4(b[buf][g][0], b[buf][g][1], b[buf][g][2], b[buf][g][3],
                    Bb + SWZ128(n * 128 + ks * 32 + b_koff));
        }
    };

    auto do_mmas = [&](int buf) {
        #pragma unroll
        for (int mt = 0; mt < 2; mt++)
            #pragma unroll
            for (int nt = 0; nt < 8; nt++) {
                int g = nt >> 1, h = (nt & 1) * 2;
                MMA16816(acc[mt][nt], a[buf][mt], b[buf][g][h], b[buf][g][h + 1]);
            }
    };

    for (int c = 0; c < 3; c++) { load_chunk(c); CP_COMMIT(); }

    for (int c = 0; c < NCHUNK; c++) {
        CP_WAIT2();
        __syncthreads();
        const int s = c & (S_STAGES - 1);
        const uint32_t Ab = base + s * STAGE_B;
        const uint32_t Bb = Ab + A_TILE_B;

        // ks-pipelined: prefetch ks+1 fragments before ks MMAs
        load_frags(0, Ab, Bb, 0);
        #pragma unroll
        for (int ks = 0; ks < 4; ks++) {
            if (ks < 3) load_frags((ks + 1) & 1, Ab, Bb, ks + 1);
            do_mmas(ks & 1);
        }

        if (c + 3 < NCHUNK) load_chunk(c + 3);
        CP_COMMIT();
    }

    // Epilogue: bias + threshold + compact candidate append (no z store)
    const int gid = lane >> 2, t4 = lane & 3;
    #pragma unroll
    for (int nt = 0; nt < 8; nt++) {
        const int gn = nBase + wn * 64 + nt * 8 + t4 * 2;
        const float2 bz = *(const float2*)(benc + gn);
        #pragma unroll
        for (int mt = 0; mt < 2; mt++) {
            #pragma unroll
            for (int q2 = 0; q2 < 2; q2++) {
                const int m = mBase + wm * 32 + mt * 16 + gid + q2 * 8;
                float v0 = acc[mt][nt][q2 * 2 + 0] + bz.x;
                float v1 = acc[mt][nt][q2 * 2 + 1] + bz.y;
                if (fabsf(v0) >= THR0) {
                    int p = atomicAdd(&g_cnt[m], 1);
                    if (p < CAP) { g_cidx[(size_t)m * CAP + p] = gn;     g_cval[(size_t)m * CAP + p] = v0; }
                }
                if (fabsf(v1) >= THR0) {
                    int p = atomicAdd(&g_cnt[m], 1);
                    if (p < CAP) { g_cidx[(size_t)m * CAP + p] = gn + 1; g_cval[(size_t)m * CAP + p] = v1; }
                }
            }
        }
    }
}

// ---------------- top-k on compact candidates --------------------------------
__global__ __launch_bounds__(256) void topk_kernel(
    float* __restrict__ z_sparse,
    const float* __restrict__ x,
    const float* __restrict__ benc)
{
    __shared__ float cv[CAP];
    __shared__ int   ci[CAP];
    __shared__ int   eidx[ECAP];
    __shared__ float ev[ECAP];
    __shared__ float xrow[DDIM];
    __shared__ float s_tau;
    __shared__ int   s_ne;

    const int row  = blockIdx.x;
    const int tid  = threadIdx.x;
    const int lane = tid & 31;
    const int wid  = tid >> 5;
    float* zs = z_sparse + (size_t)row * LDIM;

    if (tid == 0) { s_ne = 0; s_tau = -1e30f; }

    const int cnt = min(g_cnt[row], CAP);

    // load compact candidates + x row into smem
    for (int i = tid; i < cnt; i += 256) {
        cv[i] = g_cval[(size_t)row * CAP + i];
        ci[i] = g_cidx[(size_t)row * CAP + i];
    }
    for (int d = tid; d < DDIM; d += 256) xrow[d] = x[(size_t)row * DDIM + d];
    __syncthreads();

    // parallel O(n^2) rank on approx |v| to find the 64th-largest (tau)
    if (cnt > KSEL) {
        for (int i = tid; i < cnt; i += 256) {
            const float av = fabsf(cv[i]);
            int rank = 0;
            for (int j = 0; j < cnt; ++j) {
                float bv = fabsf(cv[j]);
                rank += (bv > av) || (bv == av && j < i);
            }
            if (rank == KSEL - 1) s_tau = av;   // unique thread writes
        }
    }
    __syncthreads();
    const float thr = s_tau - MARGIN2;          // cnt<=KSEL => thr=-inf (all eligible)

    // collect eligible candidates (true top-64 guaranteed inside)
    for (int i = tid; i < cnt; i += 256) {
        if (fabsf(cv[i]) >= thr) {
            int p = atomicAdd(&s_ne, 1);
            if (p < ECAP) eidx[p] = i;
        }
    }
    __syncthreads();
    const int ne = min(s_ne, ECAP);

    // exact fp32 recompute: one warp per candidate (smem xrow . fp32 W^T col)
    // NOTE: arithmetic/order must stay EXACTLY as-is (selection correctness).
    for (int a = wid; a < ne; a += 8) {
        const int col = ci[eidx[a]];
        const float4* wr = (const float4*)(g_Wt + (size_t)col * DDIM);
        const float4* xr = (const float4*)xrow;
        float p = 0.0f;
        #pragma unroll 4
        for (int d4 = lane; d4 < DDIM / 4; d4 += 32) {
            float4 w = wr[d4];
            float4 xv = xr[d4];
            p = fmaf(xv.x, w.x, p);
            p = fmaf(xv.y, w.y, p);
            p = fmaf(xv.z, w.z, p);
            p = fmaf(xv.w, w.w, p);
        }
        #pragma unroll
        for (int off = 16; off > 0; off >>= 1)
            p += __shfl_xor_sync(0xffffffffu, p, off);
        if (lane == 0) ev[a] = p + benc[col];
    }
    __syncthreads();

    // exact rank selection (|v| desc, col idx asc); rank == output slot
    for (int a = tid; a < ne; a += 256) {
        const float av = fabsf(ev[a]);
        const int   ai = ci[eidx[a]];
        int rank = 0;
        for (int j = 0; j < ne; ++j) {
            float bv = fabsf(ev[j]);
            rank += (bv > av) || (bv == av && ci[eidx[j]] < ai);
        }
        if (rank < KSEL) {
            zs[ai] = ev[a];                        // scatter into pre-zeroed row
            g_topk_idx[row * KSEL + rank] = ai;
            g_topk_val[row * KSEL + rank] = ev[a];
        }
    }
    // pad topk list if degenerate (ne < 64) — keeps decode deterministic
    const int filled = min(ne, KSEL);
    for (int t = filled + tid; t < KSEL; t += 256) {
        g_topk_idx[row * KSEL + t] = 0;
        g_topk_val[row * KSEL + t] = 0.0f;
    }
}

// ---------------- sparse decode ----------------------------------------------
__global__ __launch_bounds__(256) void decode_kernel(
    const float* __restrict__ Wd,
    const float* __restrict__ bd,
    float* __restrict__ recon)
{
    __shared__ int   sidx[KSEL];
    __shared__ float sval[KSEL];
    const int row = blockIdx.x;
    const int tid = threadIdx.x;

    if (tid < KSEL) {
        sidx[tid] = g_topk_idx[row * KSEL + tid];
        sval[tid] = g_topk_val[row * KSEL + tid];
    }
    __syncthreads();

    const int col = tid * 8;
    float4 acc0 = *(const float4*)(bd + col);
    float4 acc1 = *(const float4*)(bd + col + 4);

    #pragma unroll 4
    for (int j = 0; j < KSEL; ++j) {
        const float* wr = Wd + (size_t)sidx[j] * DDIM + col;
        float4 w0 = *(const float4*)(wr);
        float4 w1 = *(const float4*)(wr + 4);
        float v = sval[j];
        acc0.x = fmaf(v, w0.x, acc0.x);
        acc0.y = fmaf(v, w0.y, acc0.y);
        acc0.z = fmaf(v, w0.z, acc0.z);
        acc0.w = fmaf(v, w0.w, acc0.w);
        acc1.x = fmaf(v, w1.x, acc1.x);
        acc1.y = fmaf(v, w1.y, acc1.y);
        acc1.z = fmaf(v, w1.z, acc1.z);
        acc1.w = fmaf(v, w1.w, acc1.w);
    }

    float* orow = recon + (size_t)row * DDIM + col;
    *(float4*)(orow)     = acc0;
    *(float4*)(orow + 4) = acc1;
}

// ---------------- launch -----------------------------------------------------
extern "C" void kernel_launch(void* const* d_in, const int* in_sizes, int n_in,
                              void* d_out, int out_size)
{
    const float* x    = (const float*)d_in[0];
    const float* Wenc = (const float*)d_in[1];
    const float* benc = (const float*)d_in[2];
    const float* Wdec = (const float*)d_in[3];
    const float* bdec = (const float*)d_in[4];

    float* out      = (float*)d_out;
    float* recon    = out;
    float* z_sparse = out + (size_t)BDIM * DDIM;

    cudaFuncSetAttribute(encode_gemm_mma,
                         cudaFuncAttributeMaxDynamicSharedMemorySize, GEMM_DSMEM);

    // zero z_sparse FIRST: writebacks drain during converts, far from the GEMM
    zero_fill_kernel<<<((size_t)BDIM * LDIM / 4) / 256, 256>>>((float4*)z_sparse);
    init_cnt_kernel<<<BDIM / 256, 256>>>();
    convert_x_kernel<<<(BDIM * DDIM) / 256, 256>>>(x);
    convert_w_kernel<<<dim3(LDIM / 32, DDIM / 32), dim3(32, 8)>>>(Wenc);
    encode_gemm_mma<<<dim3(LDIM / 128, BDIM / 128), 256, GEMM_DSMEM>>>(benc);
    topk_kernel<<<BDIM, 256>>>(z_sparse, x, benc);
    decode_kernel<<<BDIM, 256>>>(Wdec, bdec, recon);
}

// round 12
// speedup vs baseline: 1.3292x; 1.3292x over previous
#include <cuda_runtime.h>
#include <cuda_bf16.h>
#include <cstdint>

// Problem shape (fixed)
#define BDIM 4096
#define DDIM 2048
#define LDIM 16384
#define KSEL 64

#define CAP   1024          // max candidates per row (expected ~400)
#define THR0  2.25f         // GEMM-epilogue candidate threshold on |z~|
#define MARGIN2 0.022f      // 2 * max|z~ - z| (bf16 GEMM error, 6.5 sigma)
#define ECAP  192           // max eligible (exact-recompute) candidates per row (~70)
#define RCAP  96            // max requests per column (Poisson mean 17.5)

// ---------------- device globals (scratch; no allocations allowed) ----------
__device__ __nv_bfloat16 g_Ah[(size_t)BDIM * DDIM];           // x in bf16
__device__ __nv_bfloat16 g_Bh[(size_t)LDIM * DDIM];           // W_enc^T bf16 (K-major)
__device__ float g_Wt[(size_t)LDIM * DDIM];                   // W_enc^T fp32 (columns contiguous)
__device__ int   g_cnt[BDIM];                                 // per-row candidate count
__device__ int   g_cidx[(size_t)BDIM * CAP];                  // candidate columns
__device__ float g_cval[(size_t)BDIM * CAP];                  // candidate approx values
__device__ int   g_ne[BDIM];                                  // eligible count per row
__device__ int   g_eidx[BDIM * ECAP];                         // eligible -> candidate index
__device__ float g_ev[BDIM * ECAP];                           // exact values (phase 2 output)
__device__ int   g_reqcnt[LDIM];                              // per-column request count
__device__ int   g_req[(size_t)LDIM * RCAP];                  // packed (row<<8)|slot
__device__ int   g_topk_idx[BDIM * KSEL];
__device__ float g_topk_val[BDIM * KSEL];

// ---------------- helpers ----------------------------------------------------
__device__ __forceinline__ uint32_t smem_u32(const void* p) {
    uint32_t a;
    asm("{ .reg .u64 t; cvta.to.shared.u64 t, %1; cvt.u32.u64 %0, t; }" : "=r"(a) : "l"(p));
    return a;
}
#define SWZ128(o) ((o) ^ (((o) >> 3) & 0x70))

#define CP_ASYNC16(dst, src) \
    asm volatile("cp.async.cg.shared.global [%0], [%1], 16;" :: "r"(dst), "l"(src))
#define CP_COMMIT() asm volatile("cp.async.commit_group;" ::: "memory")
#define CP_WAIT1()  asm volatile("cp.async.wait_group 1;" ::: "memory")

#define LDSM_X4(r0, r1, r2, r3, addr) \
    asm volatile("ldmatrix.sync.aligned.m8n8.x4.shared.b16 {%0,%1,%2,%3}, [%4];" \
                 : "=r"(r0), "=r"(r1), "=r"(r2), "=r"(r3) : "r"(addr))

#define MMA16816(c, a, b0, b1) \
    asm volatile("mma.sync.aligned.m16n8k16.row.col.f32.bf16.bf16.f32 " \
                 "{%0,%1,%2,%3}, {%4,%5,%6,%7}, {%8,%9}, {%0,%1,%2,%3};" \
                 : "+f"((c)[0]), "+f"((c)[1]), "+f"((c)[2]), "+f"((c)[3]) \
                 : "r"((a)[0]), "r"((a)[1]), "r"((a)[2]), "r"((a)[3]), \
                   "r"(b0), "r"(b1))

// ---------------- small kernels ----------------------------------------------
__global__ __launch_bounds__(256) void init_cnt_kernel() {
    int i = blockIdx.x * 256 + threadIdx.x;
    if (i < BDIM) { g_cnt[i] = 0; g_ne[i] = 0; }
    if (i < LDIM) g_reqcnt[i] = 0;
}

__global__ __launch_bounds__(256) void zero_fill_kernel(float4* __restrict__ p) {
    size_t i = (size_t)blockIdx.x * 256 + threadIdx.x;
    p[i] = make_float4(0.f, 0.f, 0.f, 0.f);
}

__global__ __launch_bounds__(256) void convert_x_kernel(const float* __restrict__ x) {
    size_t i = (size_t)blockIdx.x * 256 + threadIdx.x;
    g_Ah[i] = __float2bfloat16(x[i]);
}

__global__ __launch_bounds__(256) void convert_w_kernel(const float* __restrict__ W) {
    __shared__ float t[32][33];
    const int l0 = blockIdx.x * 32;
    const int d0 = blockIdx.y * 32;
    const int tx = threadIdx.x, ty = threadIdx.y;   // (32, 8)
    #pragma unroll
    for (int i = 0; i < 4; i++)
        t[ty + i * 8][tx] = W[(size_t)(d0 + ty + i * 8) * LDIM + l0 + tx];
    __syncthreads();
    #pragma unroll
    for (int i = 0; i < 4; i++) {
        float v = t[tx][ty + i * 8];
        size_t o = (size_t)(l0 + ty + i * 8) * DDIM + d0 + tx;
        g_Bh[o] = __float2bfloat16(v);
        g_Wt[o] = v;
    }
}

// ---------------- bf16 mma.sync GEMM + fused candidate extraction ------------
// CTA 128x128, 8 warps (4m x 2n), warp tile 32x64, K-chunk 64, 3-stage, 2 CTA/SM
#define S_STAGES 3
#define NCHUNK   32               // 2048 / 64
#define A_TILE_B 16384            // 128 rows * 128 B
#define STAGE_B  32768
#define GEMM_DSMEM (S_STAGES * STAGE_B + 1024)

extern __shared__ char gdsm[];

__global__ void __launch_bounds__(256, 2) encode_gemm_mma(const float* __restrict__ benc) {
    const int tid  = threadIdx.x;
    const int lane = tid & 31;
    const int wid  = tid >> 5;
    const int wm   = wid & 3;          // m offset 32*wm
    const int wn   = wid >> 2;         // n offset 64*wn
    const int mBase = blockIdx.y * 128;
    const int nBase = blockIdx.x * 128;

    const uint32_t base = (smem_u32(gdsm) + 1023u) & ~1023u;

    auto load_chunk = [&](int c) {
        const int s  = c % S_STAGES;
        const int kk = c * 64;
        const uint32_t Ab = base + s * STAGE_B;
        const uint32_t Bb = Ab + A_TILE_B;
        #pragma unroll
        for (int i = 0; i < 8; i++) {
            int t = tid + i * 256;
            if (t < 1024) {                       // A: 128 rows x 8 x 16B
                int r = t >> 3, j = t & 7;
                CP_ASYNC16(Ab + SWZ128(r * 128 + j * 16),
                           g_Ah + ((size_t)(mBase + r) * DDIM + kk + j * 8));
            } else {                              // B: 128 rows x 8 x 16B
                int u = t - 1024;
                int r = u >> 3, j = u & 7;
                CP_ASYNC16(Bb + SWZ128(r * 128 + j * 16),
                           g_Bh + ((size_t)(nBase + r) * DDIM + kk + j * 8));
            }
        }
    };

    float acc[2][8][4];
    #pragma unroll
    for (int mt = 0; mt < 2; mt++)
        #pragma unroll
        for (int nt = 0; nt < 8; nt++)
            #pragma unroll
            for (int q = 0; q < 4; q++) acc[mt][nt][q] = 0.0f;

    load_chunk(0); CP_COMMIT();
    load_chunk(1); CP_COMMIT();

    for (int c = 0; c < NCHUNK; c++) {
        CP_WAIT1();                 // chunk c's group complete
        __syncthreads();
        const int s = c % S_STAGES;
        const uint32_t Ab = base + s * STAGE_B;
        const uint32_t Bb = Ab + A_TILE_B;

        #pragma unroll
        for (int ks = 0; ks < 4; ks++) {
            uint32_t a[2][4], b[4][4];
            #pragma unroll
            for (int mt = 0; mt < 2; mt++) {
                int row = wm * 32 + mt * 16 + (lane & 15);
                int kb  = ks * 32 + ((lane >> 4) << 4);
                LDSM_X4(a[mt][0], a[mt][1], a[mt][2], a[mt][3],
                        Ab + SWZ128(row * 128 + kb));
            }
            #pragma unroll
            for (int g = 0; g < 4; g++) {
                int n  = wn * 64 + g * 16 + (lane & 7) + ((lane >> 4) << 3);
                int kb = ks * 32 + ((lane & 8) << 1);
                LDSM_X4(b[g][0], b[g][1], b[g][2], b[g][3],
                        Bb + SWZ128(n * 128 + kb));
            }
            #pragma unroll
            for (int mt = 0; mt < 2; mt++)
                #pragma unroll
                for (int nt = 0; nt < 8; nt++) {
                    int g = nt >> 1, h = (nt & 1) * 2;
                    MMA16816(acc[mt][nt], a[mt], b[g][h], b[g][h + 1]);
                }
        }

        if (c + 2 < NCHUNK) load_chunk(c + 2);
        CP_COMMIT();
    }

    // Epilogue: bias + threshold + compact candidate append (no z store)
    const int gid = lane >> 2, t4 = lane & 3;
    #pragma unroll
    for (int nt = 0; nt < 8; nt++) {
        const int gn = nBase + wn * 64 + nt * 8 + t4 * 2;
        const float2 bz = *(const float2*)(benc + gn);
        #pragma unroll
        for (int mt = 0; mt < 2; mt++) {
            #pragma unroll
            for (int q2 = 0; q2 < 2; q2++) {
                const int m = mBase + wm * 32 + mt * 16 + gid + q2 * 8;
                float v0 = acc[mt][nt][q2 * 2 + 0] + bz.x;
                float v1 = acc[mt][nt][q2 * 2 + 1] + bz.y;
                if (fabsf(v0) >= THR0) {
                    int p = atomicAdd(&g_cnt[m], 1);
                    if (p < CAP) { g_cidx[(size_t)m * CAP + p] = gn;     g_cval[(size_t)m * CAP + p] = v0; }
                }
                if (fabsf(v1) >= THR0) {
                    int p = atomicAdd(&g_cnt[m], 1);
                    if (p < CAP) { g_cidx[(size_t)m * CAP + p] = gn + 1; g_cval[(size_t)m * CAP + p] = v1; }
                }
            }
        }
    }
}

// ---------------- phase 1: tau per row + post column requests ----------------
__global__ __launch_bounds__(256) void topk_phase1() {
    __shared__ float cv[CAP];
    __shared__ int   ci[CAP];
    __shared__ float s_tau;
    __shared__ int   s_ne;

    const int row = blockIdx.x;
    const int tid = threadIdx.x;

    if (tid == 0) { s_tau = -1e30f; s_ne = 0; }

    const int cnt = min(g_cnt[row], CAP);
    for (int i = tid; i < cnt; i += 256) {
        cv[i] = g_cval[(size_t)row * CAP + i];
        ci[i] = g_cidx[(size_t)row * CAP + i];
    }
    __syncthreads();

    // parallel O(n^2) rank on approx |v|: find the 64th-largest value (tau)
    if (cnt > KSEL) {
        for (int i = tid; i < cnt; i += 256) {
            const float av = fabsf(cv[i]);
            int rank = 0;
            for (int j = 0; j < cnt; ++j) {
                float bv = fabsf(cv[j]);
                rank += (bv > av) || (bv == av && j < i);
            }
            if (rank == KSEL - 1) s_tau = av;   // value is order-independent
        }
    }
    __syncthreads();
    const float thr = s_tau - MARGIN2;

    // eligible candidates: record per-row list + post per-column requests
    for (int i = tid; i < cnt; i += 256) {
        if (fabsf(cv[i]) >= thr) {
            int a = atomicAdd(&s_ne, 1);
            if (a < ECAP) {
                g_eidx[row * ECAP + a] = i;
                int col = ci[i];
                int slot = atomicAdd(&g_reqcnt[col], 1);
                if (slot < RCAP) g_req[(size_t)col * RCAP + slot] = (row << 8) | a;
            }
        }
    }
    __syncthreads();
    if (tid == 0) g_ne[row] = min(s_ne, ECAP);
}

// ---------------- phase 2: per-column exact fp32 dots (W streamed once) ------
__global__ __launch_bounds__(128) void topk_phase2(
    const float* __restrict__ x,
    const float* __restrict__ benc)
{
    __shared__ float4 wcol[DDIM / 4];
    const int col  = blockIdx.x;
    const int tid  = threadIdx.x;
    const int lane = tid & 31;
    const int wrp  = tid >> 5;

    const int n = min(g_reqcnt[col], RCAP);
    if (n == 0) return;                        // uniform across block

    const float4* wsrc = (const float4*)(g_Wt + (size_t)col * DDIM);
    for (int d4 = tid; d4 < DDIM / 4; d4 += 128) wcol[d4] = wsrc[d4];
    __syncthreads();

    const float bc = benc[col];
    for (int q = wrp; q < n; q += 4) {
        const int e   = g_req[(size_t)col * RCAP + q];
        const int row = e >> 8;
        const int a   = e & 255;
        const float4* xr = (const float4*)(x + (size_t)row * DDIM);
        float p = 0.0f;
        #pragma unroll 4
        for (int d4 = lane; d4 < DDIM / 4; d4 += 32) {
            float4 xv = xr[d4];
            float4 wv = wcol[d4];
            p = fmaf(xv.x, wv.x, p);
            p = fmaf(xv.y, wv.y, p);
            p = fmaf(xv.z, wv.z, p);
            p = fmaf(xv.w, wv.w, p);
        }
        #pragma unroll
        for (int off = 16; off > 0; off >>= 1)
            p += __shfl_xor_sync(0xffffffffu, p, off);
        if (lane == 0) g_ev[row * ECAP + a] = p + bc;
    }
}

// ---------------- phase 3: exact rank-64 per row + scatter -------------------
__global__ __launch_bounds__(256) void topk_phase3(float* __restrict__ z_sparse) {
    __shared__ float ev[ECAP];
    __shared__ int   ec[ECAP];

    const int row = blockIdx.x;
    const int tid = threadIdx.x;
    float* zs = z_sparse + (size_t)row * LDIM;

    const int ne = g_ne[row];
    for (int a = tid; a < ne; a += 256) {
        ev[a] = g_ev[row * ECAP + a];
        int i = g_eidx[row * ECAP + a];
        ec[a] = g_cidx[(size_t)row * CAP + i];
    }
    __syncthreads();

    // exact rank selection (|v| desc, col idx asc); rank == output slot
    for (int a = tid; a < ne; a += 256) {
        const float av = fabsf(ev[a]);
        const int   ai = ec[a];
        int rank = 0;
        for (int j = 0; j < ne; ++j) {
            float bv = fabsf(ev[j]);
            rank += (bv > av) || (bv == av && ec[j] < ai);
        }
        if (rank < KSEL) {
            zs[ai] = ev[a];                      // scatter into pre-zeroed row
            g_topk_idx[row * KSEL + rank] = ai;
            g_topk_val[row * KSEL + rank] = ev[a];
        }
    }
    // pad topk list if degenerate (ne < 64)
    const int filled = min(ne, KSEL);
    for (int t = filled + tid; t < KSEL; t += 256) {
        g_topk_idx[row * KSEL + t] = 0;
        g_topk_val[row * KSEL + t] = 0.0f;
    }
}

// ---------------- sparse decode (half the columns per launch: L2-tiled) ------
__global__ __launch_bounds__(256) void decode_kernel(
    const float* __restrict__ Wd,
    const float* __restrict__ bd,
    float* __restrict__ recon,
    int colBase)
{
    __shared__ int   sidx[KSEL];
    __shared__ float sval[KSEL];
    const int row = blockIdx.x;
    const int tid = threadIdx.x;

    if (tid < KSEL) {
        sidx[tid] = g_topk_idx[row * KSEL + tid];
        sval[tid] = g_topk_val[row * KSEL + tid];
    }
    __syncthreads();

    const int col = colBase + tid * 4;          // 256 threads * 4 = 1024 cols
    float4 acc = *(const float4*)(bd + col);

    #pragma unroll 8
    for (int j = 0; j < KSEL; ++j) {
        const float4 w = *(const float4*)(Wd + (size_t)sidx[j] * DDIM + col);
        const float v = sval[j];
        acc.x = fmaf(v, w.x, acc.x);
        acc.y = fmaf(v, w.y, acc.y);
        acc.z = fmaf(v, w.z, acc.z);
        acc.w = fmaf(v, w.w, acc.w);
    }

    *(float4*)(recon + (size_t)row * DDIM + col) = acc;
}

// ---------------- launch -----------------------------------------------------
extern "C" void kernel_launch(void* const* d_in, const int* in_sizes, int n_in,
                              void* d_out, int out_size)
{
    const float* x    = (const float*)d_in[0];
    const float* Wenc = (const float*)d_in[1];
    const float* benc = (const float*)d_in[2];
    const float* Wdec = (const float*)d_in[3];
    const float* bdec = (const float*)d_in[4];

    float* out      = (float*)d_out;
    float* recon    = out;
    float* z_sparse = out + (size_t)BDIM * DDIM;

    cudaFuncSetAttribute(encode_gemm_mma,
                         cudaFuncAttributeMaxDynamicSharedMemorySize, GEMM_DSMEM);

    zero_fill_kernel<<<((size_t)BDIM * LDIM / 4) / 256, 256>>>((float4*)z_sparse);
    init_cnt_kernel<<<LDIM / 256, 256>>>();
    convert_x_kernel<<<(BDIM * DDIM) / 256, 256>>>(x);
    convert_w_kernel<<<dim3(LDIM / 32, DDIM / 32), dim3(32, 8)>>>(Wenc);
    encode_gemm_mma<<<dim3(LDIM / 128, BDIM / 128), 256, GEMM_DSMEM>>>(benc);
    topk_phase1<<<BDIM, 256>>>();
    topk_phase2<<<LDIM, 128>>>(x, benc);
    topk_phase3<<<BDIM, 256>>>(z_sparse);
    decode_kernel<<<BDIM, 256>>>(Wdec, bdec, recon, 0);
    decode_kernel<<<BDIM, 256>>>(Wdec, bdec, recon, 1024);
}